// round 3
// baseline (speedup 1.0000x reference)
#include <cuda_runtime.h>
#include <math.h>

#define T_STEPS 32
#define NN      1024
#define H       256
#define H2      512
#define LDIM    128
#define V       800
#define BB      256
#define NB      15
#define E       (T_STEPS * NN)   /* 32768 */
#define R       (E + BB)         /* 33024 */

// ---------------- scratch (device globals; no allocation allowed) ----------
__device__ float g_hbuf[(E + 1) * H];       // message hidden states (+ zero pad row E)
__device__ float g_Urh[(E + 1) * H];        // precomputed hbuf @ U_r^T (+ zero pad)
__device__ float g_stopraw[(size_t)R * H2]; // [x, cur_o] rows for stop head (+ root rows)
__device__ float g_hnei[NN * NB * H];       // gathered neighbor h rows (one step)
__device__ float g_rpre[NN * NB * H];       // gathered Urh rows (one step)
__device__ float g_xs[NN * H2];             // [x, sum_h]
__device__ float g_xg[NN * H2];             // [x, gated]
__device__ float g_z[NN * H];
__device__ float g_rx[NN * H];
__device__ float g_A[(size_t)R * (H + LDIM)];  // gathered GEMM input for heads
__device__ float g_h2[(size_t)R * H];          // relu hidden of heads
__device__ float g_big[(size_t)R * V];         // scores buffer (reused for agg)
__device__ float g_rowNll[R];
__device__ float g_rowHit[R];
__device__ float g_rowMask[R];
__device__ float g_rowBce[R];
__device__ float g_rowSAcc[R];

// ---------------- init: zero pad rows ----------------
__global__ void k_init() {
    int j = threadIdx.x;
    if (blockIdx.x == 0) g_hbuf[E * H + j] = 0.f;
    else                 g_Urh[E * H + j] = 0.f;
}

// ---------------- per-step gather ----------------
// block = node n, thread = feature j
__global__ void k_gather(int t, const float* __restrict__ emb,
                         const int* __restrict__ word_ids,
                         const int* __restrict__ h_nei_idx,
                         const int* __restrict__ o_nei_idx) {
    int n = blockIdx.x, j = threadIdx.x;
    int base = t * NN + n;
    int wid = word_ids[base];
    float x = emb[wid * H + j];
    const int* hrow = h_nei_idx + base * NB;
    const int* orow = o_nei_idx + base * NB;
    float sh = 0.f, co = 0.f;
#pragma unroll
    for (int nb = 0; nb < NB; nb++) {
        int hi = hrow[nb];
        float v = g_hbuf[hi * H + j];
        g_hnei[(n * NB + nb) * H + j] = v;
        g_rpre[(n * NB + nb) * H + j] = g_Urh[hi * H + j];
        sh += v;
    }
#pragma unroll
    for (int nb = 0; nb < NB; nb++) co += g_hbuf[orow[nb] * H + j];
    g_xs[n * H2 + j]     = x;
    g_xs[n * H2 + H + j] = sh;
    g_xg[n * H2 + j]     = x;
    g_stopraw[(size_t)base * H2 + j]     = x;
    g_stopraw[(size_t)base * H2 + H + j] = co;
}

// ---------------- gated = sum_nb sigmoid(rx + rpre) * h_nei ----------------
__global__ void k_gated() {
    int n = blockIdx.x, j = threadIdx.x;
    float rx = g_rx[n * H + j];
    float g = 0.f;
#pragma unroll
    for (int nb = 0; nb < NB; nb++) {
        float rp = g_rpre[(n * NB + nb) * H + j];
        float hv = g_hnei[(n * NB + nb) * H + j];
        float r = 1.f / (1.f + expf(-(rx + rp)));
        g += r * hv;
    }
    g_xg[n * H2 + H + j] = g;
}

// ---------------- generic fp32 GEMM: C = epi(A[M,K] @ W[Nc,K]^T) -----------
// EPI: 0=+bias, 1=sigmoid(+bias), 2=GRU-final(tanh,+z/sumh combine), 3=relu(+bias), 4=plain
template <int EPI>
__global__ void __launch_bounds__(256) k_gemm(
    const float* __restrict__ A, int lda, int M,
    const float* __restrict__ W, int Nc, int K,
    const float* __restrict__ bias,
    float* __restrict__ C, int ldc,
    const float* __restrict__ e0, const float* __restrict__ e1) {
    __shared__ float sA[16][64];
    __shared__ float sW[16][64];
    const int tid = threadIdx.x;
    const int bm = blockIdx.y * 64;
    const int bn = blockIdx.x * 64;
    const int lr = tid >> 2;           // 0..63
    const int lk = (tid & 3) << 2;     // 0,4,8,12
    const int tx = tid & 15, ty = tid >> 4;
    float acc[4][4];
#pragma unroll
    for (int i = 0; i < 4; i++)
#pragma unroll
        for (int j = 0; j < 4; j++) acc[i][j] = 0.f;

    const bool aok = (bm + lr) < M;
    const bool wok = (bn + lr) < Nc;
    const float* Ap = A + (size_t)(bm + lr) * lda + lk;
    const float* Wp = W + (size_t)(bn + lr) * K + lk;

    for (int k0 = 0; k0 < K; k0 += 16) {
        float4 a = aok ? *(const float4*)(Ap + k0) : make_float4(0.f, 0.f, 0.f, 0.f);
        float4 w = wok ? *(const float4*)(Wp + k0) : make_float4(0.f, 0.f, 0.f, 0.f);
        sA[lk + 0][lr] = a.x; sA[lk + 1][lr] = a.y; sA[lk + 2][lr] = a.z; sA[lk + 3][lr] = a.w;
        sW[lk + 0][lr] = w.x; sW[lk + 1][lr] = w.y; sW[lk + 2][lr] = w.z; sW[lk + 3][lr] = w.w;
        __syncthreads();
#pragma unroll
        for (int k = 0; k < 16; k++) {
            float4 av = *(const float4*)&sA[k][ty * 4];
            float4 wv = *(const float4*)&sW[k][tx * 4];
            acc[0][0] += av.x * wv.x; acc[0][1] += av.x * wv.y; acc[0][2] += av.x * wv.z; acc[0][3] += av.x * wv.w;
            acc[1][0] += av.y * wv.x; acc[1][1] += av.y * wv.y; acc[1][2] += av.y * wv.z; acc[1][3] += av.y * wv.w;
            acc[2][0] += av.z * wv.x; acc[2][1] += av.z * wv.y; acc[2][2] += av.z * wv.z; acc[2][3] += av.z * wv.w;
            acc[3][0] += av.w * wv.x; acc[3][1] += av.w * wv.y; acc[3][2] += av.w * wv.z; acc[3][3] += av.w * wv.w;
        }
        __syncthreads();
    }
#pragma unroll
    for (int i = 0; i < 4; i++) {
        int gr = bm + ty * 4 + i;
        if (gr >= M) continue;
#pragma unroll
        for (int j = 0; j < 4; j++) {
            int gc = bn + tx * 4 + j;
            if (gc >= Nc) continue;
            float v = acc[i][j];
            if (EPI == 0) {
                v += bias[gc];
            } else if (EPI == 1) {
                v = 1.f / (1.f + expf(-(v + bias[gc])));
            } else if (EPI == 3) {
                v = fmaxf(v + bias[gc], 0.f);
            } else if (EPI == 2) {
                float ht = tanhf(v + bias[gc]);
                float z  = e0[(size_t)gr * H + gc];
                float sh = e1[(size_t)gr * H2 + gc];
                v = (1.f - z) * sh + z * ht;
            } // EPI==4: plain
            C[(size_t)gr * ldc + gc] = v;
        }
    }
}

// ---------------- pred-head A build: [hid | xtree[ctx]] ----------------
__global__ void k_predA(const float* __restrict__ xtree, const int* __restrict__ contexts) {
    int i = blockIdx.x, j = threadIdx.x;
    if (j < H) {
        g_A[(size_t)i * (H + LDIM) + j] = (i < BB) ? 0.f : g_hbuf[(i - BB) * H + j];
    } else {
        int ctx = (i < BB) ? i : contexts[i - BB];
        g_A[(size_t)i * (H + LDIM) + j] = xtree[ctx * LDIM + (j - H)];
    }
}

// ---------------- pred row reduction: logsumexp + first-argmax -------------
__global__ void k_predReduce(const int* __restrict__ direction,
                             const int* __restrict__ pred_targets,
                             const int* __restrict__ root_word_ids) {
    int w = threadIdx.x >> 5, lane = threadIdx.x & 31;
    int gi = blockIdx.x * 8 + w;
    if (gi >= R) return;
    const float* row = g_big + (size_t)gi * V;
    float bv = -INFINITY; int bi = 0x7fffffff;
    for (int j = lane; j < V; j += 32) {
        float v = row[j];
        if (v > bv) { bv = v; bi = j; }   // strict > keeps first occurrence per lane
    }
#pragma unroll
    for (int off = 16; off; off >>= 1) {
        float ov = __shfl_xor_sync(0xffffffffu, bv, off);
        int   oi = __shfl_xor_sync(0xffffffffu, bi, off);
        if (ov > bv || (ov == bv && oi < bi)) { bv = ov; bi = oi; }
    }
    float s = 0.f;
    for (int j = lane; j < V; j += 32) s += expf(row[j] - bv);
#pragma unroll
    for (int off = 16; off; off >>= 1) s += __shfl_xor_sync(0xffffffffu, s, off);
    if (lane == 0) {
        float mask; int tgt;
        if (gi < BB) { mask = 1.f; tgt = root_word_ids[gi]; }
        else { mask = (float)direction[gi - BB]; tgt = pred_targets[gi - BB]; }
        float nll = bv + logf(s) - row[tgt];
        g_rowNll[gi]  = mask * nll;
        g_rowHit[gi]  = mask * ((bi == tgt) ? 1.f : 0.f);
        g_rowMask[gi] = mask;
    }
}

// ---------------- stop-head root rows: [emb[root] | sum hbuf[root_o_idx]] --
__global__ void k_stopRoot(const float* __restrict__ emb,
                           const int* __restrict__ root_word_ids,
                           const int* __restrict__ root_o_idx) {
    int b = blockIdx.x, j = threadIdx.x;
    int wid = root_word_ids[b];
    g_stopraw[(size_t)(E + b) * H2 + j] = emb[wid * H + j];
    float s = 0.f;
#pragma unroll
    for (int nb = 0; nb < NB; nb++) s += g_hbuf[root_o_idx[b * NB + nb] * H + j];
    g_stopraw[(size_t)(E + b) * H2 + H + j] = s;
}

// ---------------- stop-head A build: [stop_hid | xtree[ctx]] ---------------
__global__ void k_stopA(const float* __restrict__ xtree, const int* __restrict__ contexts) {
    int i = blockIdx.x, j = threadIdx.x;
    if (j < H) {
        g_A[(size_t)i * (H + LDIM) + j] = g_h2[(size_t)i * H + j];
    } else {
        int ctx = (i < E) ? contexts[i] : (i - E);
        g_A[(size_t)i * (H + LDIM) + j] = xtree[ctx * LDIM + (j - H)];
    }
}

// ---------------- stop scalar: s = agg . Uo + b; bce; acc ----------------
__global__ void k_stopDot(const float* __restrict__ Uo_w, const float* __restrict__ Uo_b,
                          const int* __restrict__ direction) {
    int w = threadIdx.x >> 5, lane = threadIdx.x & 31;
    int gi = blockIdx.x * 8 + w;
    if (gi >= R) return;
    const float* row = g_big + (size_t)gi * H;  // agg stored with ldc=H
    float s = 0.f;
#pragma unroll
    for (int k = lane; k < H; k += 32) s += row[k] * Uo_w[k];
#pragma unroll
    for (int off = 16; off; off >>= 1) s += __shfl_xor_sync(0xffffffffu, s, off);
    if (lane == 0) {
        s += Uo_b[0];
        float tgt = (gi < E) ? (float)direction[gi] : 0.f;
        float bce = fmaxf(s, 0.f) - s * tgt + log1pf(expf(-fabsf(s)));
        g_rowBce[gi] = bce;
        float pred = (s >= 0.f) ? 1.f : 0.f;
        g_rowSAcc[gi] = (pred == tgt) ? 1.f : 0.f;
    }
}

// ---------------- final deterministic reduction ----------------
__global__ void k_final(float* __restrict__ out) {
    __shared__ float sm[1024];
    int tid = threadIdx.x;
    float a0 = 0.f, a1 = 0.f, a2 = 0.f, a3 = 0.f, a4 = 0.f;
    for (int i = tid; i < R; i += 1024) {
        a0 += g_rowNll[i]; a1 += g_rowHit[i]; a2 += g_rowMask[i];
        a3 += g_rowBce[i]; a4 += g_rowSAcc[i];
    }
    auto red = [&](float v) -> float {
        sm[tid] = v; __syncthreads();
        for (int s = 512; s; s >>= 1) { if (tid < s) sm[tid] += sm[tid + s]; __syncthreads(); }
        float r = sm[0]; __syncthreads();
        return r;
    };
    float nll = red(a0), hit = red(a1), msk = red(a2), bce = red(a3), sac = red(a4);
    if (tid == 0) {
        out[0] = nll / (float)BB;   // pred_loss
        out[1] = bce / (float)BB;   // stop_loss
        out[2] = hit / msk;         // pred_acc
        out[3] = sac / (float)R;    // stop_acc
    }
}

// ---------------- launch ----------------
extern "C" void kernel_launch(void* const* d_in, const int* in_sizes, int n_in,
                              void* d_out, int out_size) {
    const float* emb    = (const float*)d_in[0];
    const float* W_z_w  = (const float*)d_in[1];
    const float* W_z_b  = (const float*)d_in[2];
    const float* W_r_w  = (const float*)d_in[3];
    const float* W_r_b  = (const float*)d_in[4];
    const float* U_r_w  = (const float*)d_in[5];
    const float* W_h_w  = (const float*)d_in[6];
    const float* W_h_b  = (const float*)d_in[7];
    const float* W_w    = (const float*)d_in[8];
    const float* W_b    = (const float*)d_in[9];
    const float* Wo_w   = (const float*)d_in[10];
    const float* Wo_b   = (const float*)d_in[11];
    const float* U_w    = (const float*)d_in[12];
    const float* U_b    = (const float*)d_in[13];
    const float* Ui_w   = (const float*)d_in[14];
    const float* Ui_b   = (const float*)d_in[15];
    const float* Uo_w   = (const float*)d_in[16];
    const float* Uo_b   = (const float*)d_in[17];
    const float* xtree  = (const float*)d_in[18];
    const int* word_ids = (const int*)d_in[19];
    const int* h_nei    = (const int*)d_in[20];
    const int* o_nei    = (const int*)d_in[21];
    const int* contexts = (const int*)d_in[22];
    const int* pred_t   = (const int*)d_in[23];
    const int* directn  = (const int*)d_in[24];
    const int* root_wid = (const int*)d_in[25];
    const int* root_oid = (const int*)d_in[26];
    float* out = (float*)d_out;

    float *p_hbuf, *p_Urh, *p_stopraw, *p_xs, *p_xg, *p_z, *p_rx, *p_A, *p_h2, *p_big;
    cudaGetSymbolAddress((void**)&p_hbuf, g_hbuf);
    cudaGetSymbolAddress((void**)&p_Urh, g_Urh);
    cudaGetSymbolAddress((void**)&p_stopraw, g_stopraw);
    cudaGetSymbolAddress((void**)&p_xs, g_xs);
    cudaGetSymbolAddress((void**)&p_xg, g_xg);
    cudaGetSymbolAddress((void**)&p_z, g_z);
    cudaGetSymbolAddress((void**)&p_rx, g_rx);
    cudaGetSymbolAddress((void**)&p_A, g_A);
    cudaGetSymbolAddress((void**)&p_h2, g_h2);
    cudaGetSymbolAddress((void**)&p_big, g_big);

    k_init<<<2, 256>>>();

    const dim3 gSmall(4, 16);   // 256 cols x 1024 rows
    for (int t = 0; t < T_STEPS; t++) {
        k_gather<<<NN, 256>>>(t, emb, word_ids, h_nei, o_nei);
        // z = sigmoid([x,sum_h] @ Wz^T + b)
        k_gemm<1><<<gSmall, 256>>>(p_xs, H2, NN, W_z_w, H, H2, W_z_b, p_z, H, nullptr, nullptr);
        // rx = x @ Wr^T + b
        k_gemm<0><<<gSmall, 256>>>(p_xs, H2, NN, W_r_w, H, H, W_r_b, p_rx, H, nullptr, nullptr);
        // gated
        k_gated<<<NN, 256>>>();
        // new_h = (1-z)*sum_h + z*tanh([x,gated]@Wh^T + b)  -> hbuf[t*N ..]
        k_gemm<2><<<gSmall, 256>>>(p_xg, H2, NN, W_h_w, H, H2, W_h_b,
                                   p_hbuf + (size_t)t * NN * H, H, p_z, p_xs + H);
        // Urh[t*N..] = new_h @ U_r^T  (precompute for future gathers)
        k_gemm<4><<<gSmall, 256>>>(p_hbuf + (size_t)t * NN * H, H, NN, U_r_w, H, H,
                                   nullptr, p_Urh + (size_t)t * NN * H, H, nullptr, nullptr);
    }

    // ---- word prediction head ----
    k_predA<<<R, 384>>>(xtree, contexts);
    k_gemm<3><<<dim3(4, 516), 256>>>(p_A, H + LDIM, R, W_w, H, H + LDIM, W_b, p_h2, H, nullptr, nullptr);
    k_gemm<0><<<dim3(13, 516), 256>>>(p_h2, H, R, Wo_w, V, H, Wo_b, p_big, V, nullptr, nullptr);
    k_predReduce<<<(R + 7) / 8, 256>>>(directn, pred_t, root_wid);

    // ---- stop head ----
    k_stopRoot<<<BB, 256>>>(emb, root_wid, root_oid);
    k_gemm<3><<<dim3(4, 516), 256>>>(p_stopraw, H2, R, Ui_w, H, H2, Ui_b, p_h2, H, nullptr, nullptr);
    k_stopA<<<R, 384>>>(xtree, contexts);
    k_gemm<3><<<dim3(4, 516), 256>>>(p_A, H + LDIM, R, U_w, H, H + LDIM, U_b, p_big, H, nullptr, nullptr);
    k_stopDot<<<(R + 7) / 8, 256>>>(Uo_w, Uo_b, directn);

    k_final<<<1, 1024>>>(out);
}

// round 4
// speedup vs baseline: 2.0958x; 2.0958x over previous
#include <cuda_runtime.h>
#include <math.h>

#define T_STEPS 32
#define NN      1024
#define H       256
#define LDIM    128
#define V       800
#define BB      256
#define NB      15
#define E       (T_STEPS * NN)   /* 32768 */
#define R       (E + BB)         /* 33024 */

// ---------------- device scratch (no allocation allowed) ----------------
__device__ float g_hbuf[(E + 1) * H];
__device__ float g_Urh[(E + 1) * H];
__device__ float g_curo[(size_t)R * H];
__device__ float g_sh[NN * H];
__device__ float g_xg[NN * H];
__device__ float g_Epre[800 * 1024];     // [E_z | E_r | E_h | E_ui] per word (biases folded)
__device__ float g_Xpu[BB * 512];        // [Xp | Xu] per context (biases folded)
__device__ float g_Wcat[1024 * H];
__device__ float g_Wx[512 * LDIM];
__device__ float g_bcat[1024];
__device__ float g_bcat2[512];
__device__ float g_Ac[(size_t)R * H];    // compacted pred-head input
__device__ float g_h2[(size_t)R * H];
__device__ float g_big[(size_t)R * V];
__device__ int   g_pidx[R];
__device__ int   g_pctx[R];
__device__ int   g_swid[R];
__device__ int   g_sctx[R];
__device__ int   g_cnt;
__device__ float g_rowNll[R];
__device__ float g_rowHit[R];
__device__ float g_rowBce[R];
__device__ float g_rowSAcc[R];

// ---------------- init: zero the pad rows ----------------
__global__ void k_init() {
    int j = threadIdx.x;
    if (blockIdx.x == 0) g_hbuf[E * H + j] = 0.f;
    else                 g_Urh[E * H + j] = 0.f;
}

// ---------------- build combined weight matrices ----------------
__global__ void k_prep(const float* __restrict__ Wz, const float* __restrict__ Wzb,
                       const float* __restrict__ Wr, const float* __restrict__ Wrb,
                       const float* __restrict__ Wh, const float* __restrict__ Whb,
                       const float* __restrict__ Ui, const float* __restrict__ Uib,
                       const float* __restrict__ Ww, const float* __restrict__ Wb,
                       const float* __restrict__ Uw, const float* __restrict__ Ub) {
    int r = blockIdx.x, j = threadIdx.x;
    if (r < 1024) {
        int rr = r & 255;
        float v, b;
        if (r < 256)      { v = Wz[rr * 512 + j]; b = Wzb[rr]; }
        else if (r < 512) { v = Wr[rr * 256 + j]; b = Wrb[rr]; }
        else if (r < 768) { v = Wh[rr * 512 + j]; b = Whb[rr]; }
        else              { v = Ui[rr * 512 + j]; b = Uib[rr]; }
        g_Wcat[r * H + j] = v;
        if (j == 0) g_bcat[r] = b;
    } else {
        int r2 = r - 1024;
        int rr = r2 & 255;
        if (j < LDIM) {
            float v = (r2 < 256) ? Ww[rr * 384 + 256 + j] : Uw[rr * 384 + 256 + j];
            g_Wx[r2 * LDIM + j] = v;
        }
        if (j == 0) g_bcat2[r2] = (r2 < 256) ? Wb[rr] : Ub[rr];
    }
}

// ---------------- generic fp32 GEMM: C = epi(A[M,K] @ W[Nc,K]^T) ----------
// EPI: 0=plain  1=+bias  2=relu(+addMat[addIdx[row]])
template <int BM, int EPI>
__global__ void __launch_bounds__(256) k_gemm(
    const float* __restrict__ A, int lda, int Mh, const int* __restrict__ Mptr,
    const float* __restrict__ W, int ldw, int Nc, int K,
    const float* __restrict__ bias,
    float* __restrict__ C, int ldc,
    const float* __restrict__ addMat, int addStride, const int* __restrict__ addIdx) {
    const int M = Mptr ? *Mptr : Mh;
    const int bm = blockIdx.y * BM;
    if (bm >= M) return;
    const int bn = blockIdx.x * 64;
    __shared__ __align__(16) float sA[16][BM];
    __shared__ __align__(16) float sW[16][64];
    const int tid = threadIdx.x;
    constexpr int TM = BM / 16;
    const int tx = tid & 15, ty = tid >> 4;
    float acc[TM][4];
#pragma unroll
    for (int i = 0; i < TM; i++)
#pragma unroll
        for (int j = 0; j < 4; j++) acc[i][j] = 0.f;
    const int lr = tid >> 2, lk = (tid & 3) << 2;
    const bool wok = (bn + lr) < Nc;
    const bool aok = (lr < BM) && ((bm + lr) < M);
    const float* Wp = W + (size_t)(bn + lr) * ldw + lk;
    const float* Ap = A + (size_t)(bm + (lr < BM ? lr : 0)) * lda + lk;

    for (int k0 = 0; k0 < K; k0 += 16) {
        float4 w = wok ? *(const float4*)(Wp + k0) : make_float4(0.f, 0.f, 0.f, 0.f);
        sW[lk + 0][lr] = w.x; sW[lk + 1][lr] = w.y; sW[lk + 2][lr] = w.z; sW[lk + 3][lr] = w.w;
        if (lr < BM) {
            float4 a = aok ? *(const float4*)(Ap + k0) : make_float4(0.f, 0.f, 0.f, 0.f);
            sA[lk + 0][lr] = a.x; sA[lk + 1][lr] = a.y; sA[lk + 2][lr] = a.z; sA[lk + 3][lr] = a.w;
        }
        __syncthreads();
#pragma unroll
        for (int k = 0; k < 16; k++) {
            float4 wv = *(const float4*)&sW[k][tx * 4];
            if constexpr (TM == 4) {
                float4 av = *(const float4*)&sA[k][ty * 4];
                acc[0][0] += av.x * wv.x; acc[0][1] += av.x * wv.y; acc[0][2] += av.x * wv.z; acc[0][3] += av.x * wv.w;
                acc[1][0] += av.y * wv.x; acc[1][1] += av.y * wv.y; acc[1][2] += av.y * wv.z; acc[1][3] += av.y * wv.w;
                acc[2][0] += av.z * wv.x; acc[2][1] += av.z * wv.y; acc[2][2] += av.z * wv.z; acc[2][3] += av.z * wv.w;
                acc[3][0] += av.w * wv.x; acc[3][1] += av.w * wv.y; acc[3][2] += av.w * wv.z; acc[3][3] += av.w * wv.w;
            } else {
                float2 av = *(const float2*)&sA[k][ty * 2];
                acc[0][0] += av.x * wv.x; acc[0][1] += av.x * wv.y; acc[0][2] += av.x * wv.z; acc[0][3] += av.x * wv.w;
                acc[1][0] += av.y * wv.x; acc[1][1] += av.y * wv.y; acc[1][2] += av.y * wv.z; acc[1][3] += av.y * wv.w;
            }
        }
        __syncthreads();
    }
#pragma unroll
    for (int i = 0; i < TM; i++) {
        int gr = bm + ty * TM + i;
        if (gr >= M) continue;
        int id = 0;
        if (EPI == 2) id = addIdx[gr];
#pragma unroll
        for (int j = 0; j < 4; j++) {
            int gc = bn + tx * 4 + j;
            if (gc >= Nc) continue;
            float v = acc[i][j];
            if (EPI == 1)      v += bias[gc];
            else if (EPI == 2) v = fmaxf(v + addMat[(size_t)id * addStride + gc], 0.f);
            C[(size_t)gr * ldc + gc] = v;
        }
    }
}

// ---------------- per-step gather (gated fused in-register) ----------------
__global__ void k_gather(int t, const int* __restrict__ word_ids,
                         const int* __restrict__ h_nei, const int* __restrict__ o_nei,
                         const int* __restrict__ contexts) {
    __shared__ int s_hi[NB], s_oi[NB], s_wid;
    int n = blockIdx.x, j = threadIdx.x;
    int base = t * NN + n;
    if (j < NB) s_hi[j] = h_nei[base * NB + j];
    else if (j >= 32 && j < 32 + NB) s_oi[j - 32] = o_nei[base * NB + j - 32];
    if (j == 0) {
        int w = word_ids[base];
        s_wid = w;
        g_swid[base] = w;
        g_sctx[base] = contexts[base];
    }
    __syncthreads();
    int wid = s_wid;
    float rx = g_Epre[(size_t)wid * 1024 + 256 + j];   // E_r (W_r_b folded)
    float sh = 0.f, g = 0.f, co = 0.f;
#pragma unroll
    for (int nb = 0; nb < NB; nb++) {
        int hi = s_hi[nb];
        float v  = g_hbuf[(size_t)hi * H + j];
        float rp = g_Urh[(size_t)hi * H + j];
        sh += v;
        g  += v / (1.f + expf(-(rx + rp)));
    }
#pragma unroll
    for (int nb = 0; nb < NB; nb++) co += g_hbuf[(size_t)s_oi[nb] * H + j];
    g_sh[n * H + j] = sh;
    g_xg[n * H + j] = g;
    g_curo[(size_t)base * H + j] = co;
}

// ---------------- fused z/h GEMM + GRU combine -----------------------------
// accZ = sum_h @ Wz_h^T ; accH = gated @ Wh_h^T ;
// z = sig(accZ + E_z[wid]) ; newh = (1-z)*sum_h + z*tanh(accH + E_h[wid])
__global__ void __launch_bounds__(256) k_gemmZH(
    const float* __restrict__ Wzh, const float* __restrict__ Whh,  // +256-offset, ldw=512
    const int* __restrict__ wid_t, float* __restrict__ hout) {
    const int bm = blockIdx.y * 32, bn = blockIdx.x * 64;
    __shared__ __align__(16) float sA1[16][32], sA2[16][32];
    __shared__ __align__(16) float sW1[16][64], sW2[16][64];
    const int tid = threadIdx.x;
    const int tx = tid & 15, ty = tid >> 4;
    float accZ[2][4], accH[2][4];
#pragma unroll
    for (int i = 0; i < 2; i++)
#pragma unroll
        for (int j = 0; j < 4; j++) { accZ[i][j] = 0.f; accH[i][j] = 0.f; }
    const int lr = tid >> 2, lk = (tid & 3) << 2;
    const float* Wzp = Wzh + (size_t)(bn + lr) * 512 + lk;
    const float* Whp = Whh + (size_t)(bn + lr) * 512 + lk;
    const int half = tid >> 7;               // 0: load sA1(sum_h), 1: load sA2(gated)
    const int lar = (tid & 127) >> 2;        // 0..31
    const float* Ap = (half ? g_xg : g_sh) + (size_t)(bm + lar) * H + lk;

    for (int k0 = 0; k0 < H; k0 += 16) {
        float4 w1 = *(const float4*)(Wzp + k0);
        float4 w2 = *(const float4*)(Whp + k0);
        float4 a  = *(const float4*)(Ap + k0);
        sW1[lk + 0][lr] = w1.x; sW1[lk + 1][lr] = w1.y; sW1[lk + 2][lr] = w1.z; sW1[lk + 3][lr] = w1.w;
        sW2[lk + 0][lr] = w2.x; sW2[lk + 1][lr] = w2.y; sW2[lk + 2][lr] = w2.z; sW2[lk + 3][lr] = w2.w;
        if (half) { sA2[lk + 0][lar] = a.x; sA2[lk + 1][lar] = a.y; sA2[lk + 2][lar] = a.z; sA2[lk + 3][lar] = a.w; }
        else      { sA1[lk + 0][lar] = a.x; sA1[lk + 1][lar] = a.y; sA1[lk + 2][lar] = a.z; sA1[lk + 3][lar] = a.w; }
        __syncthreads();
#pragma unroll
        for (int k = 0; k < 16; k++) {
            float4 w1v = *(const float4*)&sW1[k][tx * 4];
            float4 w2v = *(const float4*)&sW2[k][tx * 4];
            float2 a1 = *(const float2*)&sA1[k][ty * 2];
            float2 a2 = *(const float2*)&sA2[k][ty * 2];
            accZ[0][0] += a1.x * w1v.x; accZ[0][1] += a1.x * w1v.y; accZ[0][2] += a1.x * w1v.z; accZ[0][3] += a1.x * w1v.w;
            accZ[1][0] += a1.y * w1v.x; accZ[1][1] += a1.y * w1v.y; accZ[1][2] += a1.y * w1v.z; accZ[1][3] += a1.y * w1v.w;
            accH[0][0] += a2.x * w2v.x; accH[0][1] += a2.x * w2v.y; accH[0][2] += a2.x * w2v.z; accH[0][3] += a2.x * w2v.w;
            accH[1][0] += a2.y * w2v.x; accH[1][1] += a2.y * w2v.y; accH[1][2] += a2.y * w2v.z; accH[1][3] += a2.y * w2v.w;
        }
        __syncthreads();
    }
#pragma unroll
    for (int i = 0; i < 2; i++) {
        int gr = bm + ty * 2 + i;
        int wd = wid_t[gr];
        const float* ez = g_Epre + (size_t)wd * 1024;      // E_z at +0, E_h at +512
#pragma unroll
        for (int j = 0; j < 4; j++) {
            int gc = bn + tx * 4 + j;
            float z  = 1.f / (1.f + expf(-(accZ[i][j] + ez[gc])));
            float ht = tanhf(accH[i][j] + ez[512 + gc]);
            float sh = g_sh[(size_t)gr * H + gc];
            hout[(size_t)gr * H + gc] = (1.f - z) * sh + z * ht;
        }
    }
}

// ---------------- compact pred rows (deterministic single-block scan) ------
__global__ void k_compact(const int* __restrict__ direction, const int* __restrict__ contexts) {
    __shared__ int warpsum[32];
    __shared__ int sbase;
    int tid = threadIdx.x;
    int lane = tid & 31, w = tid >> 5;
    if (tid == 0) sbase = 0;
    __syncthreads();
    for (int chunk = 0; chunk < R; chunk += 1024) {
        int i = chunk + tid;
        int m = 0;
        if (i < R) m = (i < BB) ? 1 : (direction[i - BB] != 0);
        unsigned bal = __ballot_sync(0xffffffffu, m);
        int pre = __popc(bal & ((1u << lane) - 1u));
        if (lane == 0) warpsum[w] = __popc(bal);
        __syncthreads();
        if (tid < 32) {
            int v = warpsum[tid];
#pragma unroll
            for (int off = 1; off < 32; off <<= 1) {
                int o = __shfl_up_sync(0xffffffffu, v, off);
                if (tid >= off) v += o;
            }
            warpsum[tid] = v;
        }
        __syncthreads();
        int wbase = (w == 0) ? 0 : warpsum[w - 1];
        if (m) {
            int pos = sbase + wbase + pre;
            g_pidx[pos] = i;
            g_pctx[pos] = (i < BB) ? i : contexts[i - BB];
        }
        __syncthreads();
        if (tid == 0) sbase += warpsum[31];
        __syncthreads();
    }
    if (tid == 0) g_cnt = sbase;
}

// ---------------- build compacted pred A ----------------
__global__ void k_predAc() {
    int r = blockIdx.x;
    if (r >= g_cnt) return;
    int pi = g_pidx[r];
    int j = threadIdx.x;
    g_Ac[(size_t)r * H + j] = (pi < BB) ? 0.f : g_hbuf[(size_t)(pi - BB) * H + j];
}

// ---------------- pred row reduction ----------------
__global__ void k_predReduce(const int* __restrict__ pred_targets,
                             const int* __restrict__ root_word_ids) {
    int w = threadIdx.x >> 5, lane = threadIdx.x & 31;
    int r = blockIdx.x * 8 + w;
    if (r >= g_cnt) return;
    int gi = g_pidx[r];
    const float* row = g_big + (size_t)r * V;
    float bv = -INFINITY; int bi = 0x7fffffff;
    for (int j = lane; j < V; j += 32) {
        float v = row[j];
        if (v > bv) { bv = v; bi = j; }
    }
#pragma unroll
    for (int off = 16; off; off >>= 1) {
        float ov = __shfl_xor_sync(0xffffffffu, bv, off);
        int   oi = __shfl_xor_sync(0xffffffffu, bi, off);
        if (ov > bv || (ov == bv && oi < bi)) { bv = ov; bi = oi; }
    }
    float s = 0.f;
    for (int j = lane; j < V; j += 32) s += expf(row[j] - bv);
#pragma unroll
    for (int off = 16; off; off >>= 1) s += __shfl_xor_sync(0xffffffffu, s, off);
    if (lane == 0) {
        int tgt = (gi < BB) ? root_word_ids[gi] : pred_targets[gi - BB];
        g_rowNll[r] = bv + logf(s) - row[tgt];
        g_rowHit[r] = (bi == tgt) ? 1.f : 0.f;
    }
}

// ---------------- stop-head root rows ----------------
__global__ void k_stopRoot(const int* __restrict__ root_word_ids,
                           const int* __restrict__ root_o_idx) {
    int b = blockIdx.x, j = threadIdx.x;
    float s = 0.f;
#pragma unroll
    for (int nb = 0; nb < NB; nb++) s += g_hbuf[(size_t)root_o_idx[b * NB + nb] * H + j];
    g_curo[(size_t)(E + b) * H + j] = s;
    if (j == 0) { g_swid[E + b] = root_word_ids[b]; g_sctx[E + b] = b; }
}

// ---------------- stop scalar dot + bce ----------------
__global__ void k_stopDot(const float* __restrict__ Uo_w, const float* __restrict__ Uo_b,
                          const int* __restrict__ direction) {
    int w = threadIdx.x >> 5, lane = threadIdx.x & 31;
    int gi = blockIdx.x * 8 + w;
    if (gi >= R) return;
    const float* row = g_big + (size_t)gi * H;
    float s = 0.f;
#pragma unroll
    for (int k = lane; k < H; k += 32) s += row[k] * Uo_w[k];
#pragma unroll
    for (int off = 16; off; off >>= 1) s += __shfl_xor_sync(0xffffffffu, s, off);
    if (lane == 0) {
        s += Uo_b[0];
        float tgt = (gi < E) ? (float)direction[gi] : 0.f;
        g_rowBce[gi] = fmaxf(s, 0.f) - s * tgt + log1pf(expf(-fabsf(s)));
        float pred = (s >= 0.f) ? 1.f : 0.f;
        g_rowSAcc[gi] = (pred == tgt) ? 1.f : 0.f;
    }
}

// ---------------- final deterministic reduction ----------------
__global__ void k_final(float* __restrict__ out) {
    __shared__ float sm[1024];
    int tid = threadIdx.x;
    int cnt = g_cnt;
    float a0 = 0.f, a1 = 0.f, a3 = 0.f, a4 = 0.f;
    for (int i = tid; i < cnt; i += 1024) { a0 += g_rowNll[i]; a1 += g_rowHit[i]; }
    for (int i = tid; i < R; i += 1024)   { a3 += g_rowBce[i]; a4 += g_rowSAcc[i]; }
    auto red = [&](float v) -> float {
        sm[tid] = v; __syncthreads();
        for (int s = 512; s; s >>= 1) { if (tid < s) sm[tid] += sm[tid + s]; __syncthreads(); }
        float r = sm[0]; __syncthreads();
        return r;
    };
    float nll = red(a0), hit = red(a1), bce = red(a3), sac = red(a4);
    if (tid == 0) {
        out[0] = nll / (float)BB;
        out[1] = bce / (float)BB;
        out[2] = hit / (float)cnt;
        out[3] = sac / (float)R;
    }
}

// ---------------- launch ----------------
extern "C" void kernel_launch(void* const* d_in, const int* in_sizes, int n_in,
                              void* d_out, int out_size) {
    const float* emb    = (const float*)d_in[0];
    const float* W_z_w  = (const float*)d_in[1];
    const float* W_z_b  = (const float*)d_in[2];
    const float* W_r_w  = (const float*)d_in[3];
    const float* W_r_b  = (const float*)d_in[4];
    const float* U_r_w  = (const float*)d_in[5];
    const float* W_h_w  = (const float*)d_in[6];
    const float* W_h_b  = (const float*)d_in[7];
    const float* W_w    = (const float*)d_in[8];
    const float* W_b    = (const float*)d_in[9];
    const float* Wo_w   = (const float*)d_in[10];
    const float* Wo_b   = (const float*)d_in[11];
    const float* U_w    = (const float*)d_in[12];
    const float* U_b    = (const float*)d_in[13];
    const float* Ui_w   = (const float*)d_in[14];
    const float* Ui_b   = (const float*)d_in[15];
    const float* Uo_w   = (const float*)d_in[16];
    const float* Uo_b   = (const float*)d_in[17];
    const float* xtree  = (const float*)d_in[18];
    const int* word_ids = (const int*)d_in[19];
    const int* h_nei    = (const int*)d_in[20];
    const int* o_nei    = (const int*)d_in[21];
    const int* contexts = (const int*)d_in[22];
    const int* pred_t   = (const int*)d_in[23];
    const int* directn  = (const int*)d_in[24];
    const int* root_wid = (const int*)d_in[25];
    const int* root_oid = (const int*)d_in[26];
    float* out = (float*)d_out;

    float *p_hbuf, *p_Urh, *p_curo, *p_Epre, *p_Xpu, *p_Wcat, *p_Wx, *p_bcat, *p_bcat2,
          *p_Ac, *p_h2, *p_big;
    int *p_cnt, *p_pctx, *p_swid, *p_sctx;
    cudaGetSymbolAddress((void**)&p_hbuf, g_hbuf);
    cudaGetSymbolAddress((void**)&p_Urh, g_Urh);
    cudaGetSymbolAddress((void**)&p_curo, g_curo);
    cudaGetSymbolAddress((void**)&p_Epre, g_Epre);
    cudaGetSymbolAddress((void**)&p_Xpu, g_Xpu);
    cudaGetSymbolAddress((void**)&p_Wcat, g_Wcat);
    cudaGetSymbolAddress((void**)&p_Wx, g_Wx);
    cudaGetSymbolAddress((void**)&p_bcat, g_bcat);
    cudaGetSymbolAddress((void**)&p_bcat2, g_bcat2);
    cudaGetSymbolAddress((void**)&p_Ac, g_Ac);
    cudaGetSymbolAddress((void**)&p_h2, g_h2);
    cudaGetSymbolAddress((void**)&p_big, g_big);
    cudaGetSymbolAddress((void**)&p_cnt, g_cnt);
    cudaGetSymbolAddress((void**)&p_pctx, g_pctx);
    cudaGetSymbolAddress((void**)&p_swid, g_swid);
    cudaGetSymbolAddress((void**)&p_sctx, g_sctx);

    // ---- one-time precomputes ----
    k_init<<<2, 256>>>();
    k_prep<<<1536, 256>>>(W_z_w, W_z_b, W_r_w, W_r_b, W_h_w, W_h_b, Ui_w, Ui_b,
                          W_w, W_b, U_w, U_b);
    // Epre = emb @ Wcat^T + bcat   (800 x 1024)
    k_gemm<64, 1><<<dim3(16, 13), 256>>>(emb, H, 800, nullptr, p_Wcat, H, 1024, H,
                                         p_bcat, p_Epre, 1024, nullptr, 0, nullptr);
    // Xpu = xtree @ Wx^T + bcat2   (256 x 512)
    k_gemm<64, 1><<<dim3(8, 4), 256>>>(xtree, LDIM, BB, nullptr, p_Wx, LDIM, 512, LDIM,
                                       p_bcat2, p_Xpu, 512, nullptr, 0, nullptr);

    // ---- recurrent loop: 3 launches/step ----
    for (int t = 0; t < T_STEPS; t++) {
        k_gather<<<NN, 256>>>(t, word_ids, h_nei, o_nei, contexts);
        k_gemmZH<<<dim3(4, 32), 256>>>(W_z_w + 256, W_h_w + 256, word_ids + t * NN,
                                       p_hbuf + (size_t)t * NN * H);
        k_gemm<32, 0><<<dim3(4, 32), 256>>>(p_hbuf + (size_t)t * NN * H, H, NN, nullptr,
                                            U_r_w, H, H, H, nullptr,
                                            p_Urh + (size_t)t * NN * H, H, nullptr, 0, nullptr);
    }

    // ---- word prediction head (mask-compacted) ----
    k_compact<<<1, 1024>>>(directn, contexts);
    k_predAc<<<R, 256>>>();
    // h2 = relu(Ac @ Ww_hid^T + Xp[ctx])
    k_gemm<64, 2><<<dim3(4, 516), 256>>>(p_Ac, H, R, p_cnt, W_w, 384, H, H,
                                         nullptr, p_h2, H, p_Xpu, 512, p_pctx);
    // scores = h2 @ Wo^T + Wo_b
    k_gemm<64, 1><<<dim3(13, 516), 256>>>(p_h2, H, R, p_cnt, Wo_w, H, V, H,
                                          Wo_b, p_big, V, nullptr, 0, nullptr);
    k_predReduce<<<(R + 7) / 8, 256>>>(pred_t, root_wid);

    // ---- stop head (all rows) ----
    k_stopRoot<<<BB, 256>>>(root_wid, root_oid);
    // h2 = relu(curo @ Ui_h^T + E_ui[wid])
    k_gemm<64, 2><<<dim3(4, 516), 256>>>(p_curo, H, R, nullptr, Ui_w + 256, 512, H, H,
                                         nullptr, p_h2, H, p_Epre + 768, 1024, p_swid);
    // agg = relu(h2 @ U_hid^T + Xu[ctx])
    k_gemm<64, 2><<<dim3(4, 516), 256>>>(p_h2, H, R, nullptr, U_w, 384, H, H,
                                         nullptr, p_big, H, p_Xpu + 256, 512, p_sctx);
    k_stopDot<<<(R + 7) / 8, 256>>>(Uo_w, Uo_b, directn);

    k_final<<<1, 1024>>>(out);
}